// round 11
// baseline (speedup 1.0000x reference)
#include <cuda_runtime.h>
#include <cuda_fp16.h>

#define GRID_SZ 256
#define BRICKS 128              // bricks per axis (2x2x2 cells per brick)
#define NVOX (GRID_SZ * GRID_SZ * GRID_SZ)

// 32 MB fp16 difference volume in 2x2x2-brick layout:
//   brick = ((z>>1)*128 + (y>>1))*128 + (x>>1)
//   cell  = (z&1)*4 + (y&1)*2 + (x&1)        (8 halves = 16 B per brick)
// One red.global.add.noftz.v4.f16x2 covers a whole brick.
// Zero-initialized at load; the reduce kernel re-zeros every chunk it reads,
// preserving the invariant across graph replays.
// Working set (32 MB volume + 72 MB inputs) fits in the 126 MB L2: default
// cache policy everywhere so it all stays resident across graph replays.
__device__ __align__(16) __half g_hvol[NVOX];

__device__ __forceinline__ void red_add_v4_h2(__half* addr, unsigned h0,
                                              unsigned h1, unsigned h2_,
                                              unsigned h3) {
    asm volatile("red.global.add.noftz.v4.f16x2 [%0], {%1,%2,%3,%4};"
                 :: "l"(addr), "r"(h0), "r"(h1), "r"(h2_), "r"(h3)
                 : "memory");
}

// Per-axis decomposition of corner pair {c0, c0+1} into up to 2 bricks.
// w0/w1 = weight destined for in-brick position 0 / 1 on that axis.
struct Axis {
    int n;
    int b[2];
    float w0[2], w1[2];
};

__device__ __forceinline__ Axis axis_decomp(int c0, float wlo, float whi) {
    Axis a;
    a.n = 0;
    int bA = c0 >> 1;  // arithmetic shift: c0=-1 -> -1 (rejected below)
    if (!(c0 & 1)) {
        if ((unsigned)bA < BRICKS) {
            a.b[0] = bA; a.w0[0] = wlo; a.w1[0] = whi; a.n = 1;
        }
    } else {
        if ((unsigned)bA < BRICKS) {
            a.b[a.n] = bA; a.w0[a.n] = 0.0f; a.w1[a.n] = wlo; a.n++;
        }
        int bB = bA + 1;
        if ((unsigned)bB < BRICKS) {
            a.b[a.n] = bB; a.w0[a.n] = whi; a.w1[a.n] = 0.0f; a.n++;
        }
    }
    return a;
}

__device__ __forceinline__ void splat(float px, float py, float pz, float s) {
    // Match reference arithmetic exactly: p = ((g+1)*size - 1) * 0.5
    float x = ((px + 1.0f) * 256.0f - 1.0f) * 0.5f;
    float y = ((py + 1.0f) * 256.0f - 1.0f) * 0.5f;
    float z = ((pz + 1.0f) * 256.0f - 1.0f) * 0.5f;
    float x0f = floorf(x), y0f = floorf(y), z0f = floorf(z);
    int x0 = (int)x0f, y0 = (int)y0f, z0 = (int)z0f;
    float fx = x - x0f, fy = y - y0f, fz = z - z0f;

    Axis ax = axis_decomp(x0, 1.0f - fx, fx);
    Axis ay = axis_decomp(y0, 1.0f - fy, fy);
    Axis az = axis_decomp(z0, (1.0f - fz) * s, fz * s);  // fold sign into z

#pragma unroll
    for (int i = 0; i < 2; i++) {
        if (i >= az.n) break;
        float t0 = az.w0[i], t1 = az.w1[i];
        int zb = az.b[i] * BRICKS;
#pragma unroll
        for (int j = 0; j < 2; j++) {
            if (j >= ay.n) break;
            float a00 = t0 * ay.w0[j];  // z0,y0
            float a01 = t0 * ay.w1[j];  // z0,y1
            float a10 = t1 * ay.w0[j];  // z1,y0
            float a11 = t1 * ay.w1[j];  // z1,y1
            int rowb = (zb + ay.b[j]) * BRICKS;
#pragma unroll
            for (int k = 0; k < 2; k++) {
                if (k >= ax.n) break;
                float u0 = ax.w0[k], u1 = ax.w1[k];
                __half* p = g_hvol + (size_t)(rowb + ax.b[k]) * 8;
                // h2 lanes are x0,x1 within cell pairs (z,y) fixed:
                __half2 q0 = __floats2half2_rn(a00 * u0, a00 * u1); // z0y0
                __half2 q1 = __floats2half2_rn(a01 * u0, a01 * u1); // z0y1
                __half2 q2 = __floats2half2_rn(a10 * u0, a10 * u1); // z1y0
                __half2 q3 = __floats2half2_rn(a11 * u0, a11 * u1); // z1y1
                red_add_v4_h2(p,
                              *(unsigned*)&q0, *(unsigned*)&q1,
                              *(unsigned*)&q2, *(unsigned*)&q3);
            }
        }
    }
}

__global__ void scatter_kernel(const float* __restrict__ pred,
                               const float* __restrict__ gt,
                               const float* __restrict__ coords,
                               float* __restrict__ out, int n) {
    int i = blockIdx.x * blockDim.x + threadIdx.x;
    if (i == 0) out[0] = 0.0f;  // reduce kernel runs after us in stream order
    if (i >= n) return;

    // Default cache policy: inputs stay L2-resident across graph replays
    // (whole working set fits in L2).
    float cx = coords[3 * i + 0];
    float cy = coords[3 * i + 1];
    float cz = coords[3 * i + 2];
    float p0 = pred[3 * i + 0];
    float p1 = pred[3 * i + 1];
    float p2 = pred[3 * i + 2];
    float g0 = gt[3 * i + 0];
    float g1 = gt[3 * i + 1];
    float g2 = gt[3 * i + 2];

    splat(cx + p0, cy + p1, cz + p2,  1.0f);
    splat(cx + g0, cy + g1, cz + g2, -1.0f);
}

__device__ __forceinline__ float huber(float d) {
    float ad = fabsf(d);
    return (ad <= 1.0f) ? 0.5f * d * d : (ad - 0.5f);
}

__device__ __forceinline__ float huber_h2(unsigned h2bits) {
    __half2 h = *(__half2*)&h2bits;
    float2 f = __half22float2(h);
    return huber(f.x) + huber(f.y);
}

// 512 blocks x 256 threads; each thread handles exactly 16 uint4 (8 halves
// each) at stride RED_TOTAL -> 16 independent loads in flight (MLP 16).
// Zero-stores carry no data dependency on the loads, so they issue as a
// second wave. NVOX/8 = 2097152 = 16 * 131072 exactly -> no bounds checks.
#define RED_BLOCKS 512
#define RED_THREADS 256
#define RED_TOTAL (RED_BLOCKS * RED_THREADS)
#define RED_ITERS 16

__global__ void __launch_bounds__(RED_THREADS)
huber_reduce_kernel(float* __restrict__ out) {
    uint4* v = reinterpret_cast<uint4*>(g_hvol);
    const int tid = blockIdx.x * RED_THREADS + threadIdx.x;
    const uint4 zero = make_uint4(0u, 0u, 0u, 0u);

    uint4 a[RED_ITERS];
#pragma unroll
    for (int k = 0; k < RED_ITERS; k++)
        a[k] = v[tid + k * RED_TOTAL];

    // Re-zero for the next graph replay (zeros land in L2 -> next scatter's
    // REDs find the volume resident).
#pragma unroll
    for (int k = 0; k < RED_ITERS; k++)
        v[tid + k * RED_TOTAL] = zero;

    float acc = 0.0f;
#pragma unroll
    for (int k = 0; k < RED_ITERS; k++) {
        acc += huber_h2(a[k].x) + huber_h2(a[k].y)
             + huber_h2(a[k].z) + huber_h2(a[k].w);
    }

    // warp reduce
#pragma unroll
    for (int o = 16; o; o >>= 1) acc += __shfl_xor_sync(0xFFFFFFFFu, acc, o);

    __shared__ float sm[RED_THREADS / 32];
    int lane = threadIdx.x & 31;
    int wid = threadIdx.x >> 5;
    if (lane == 0) sm[wid] = acc;
    __syncthreads();
    if (wid == 0) {
        float vv = (lane < (RED_THREADS / 32)) ? sm[lane] : 0.0f;
#pragma unroll
        for (int o = 16; o; o >>= 1) vv += __shfl_xor_sync(0xFFFFFFFFu, vv, o);
        if (lane == 0) atomicAdd(out, vv);
    }
}

extern "C" void kernel_launch(void* const* d_in, const int* in_sizes, int n_in,
                              void* d_out, int out_size) {
    const float* pred   = (const float*)d_in[0];
    const float* gt     = (const float*)d_in[1];
    const float* coords = (const float*)d_in[2];
    float* out = (float*)d_out;

    int n = in_sizes[0] / 3;  // N_POINTS

    int threads = 256;
    int blocks = (n + threads - 1) / threads;
    scatter_kernel<<<blocks, threads>>>(pred, gt, coords, out, n);

    huber_reduce_kernel<<<RED_BLOCKS, RED_THREADS>>>(out);
}

// round 12
// speedup vs baseline: 1.0232x; 1.0232x over previous
#include <cuda_runtime.h>
#include <cuda_fp16.h>

#define GRID_SZ 256
#define BRICKS 128              // bricks per axis (2x2x2 cells per brick)
#define NVOX (GRID_SZ * GRID_SZ * GRID_SZ)

// 32 MB fp16 difference volume in 2x2x2-brick layout:
//   brick = ((z>>1)*128 + (y>>1))*128 + (x>>1)
//   cell  = (z&1)*4 + (y&1)*2 + (x&1)        (8 halves = 16 B per brick)
// One red.global.add.noftz.v4.f16x2 covers a whole brick.
// Zero-initialized at load; the reduce kernel re-zeros every chunk it reads,
// preserving the invariant across graph replays.
__device__ __align__(16) __half g_hvol[NVOX];

__device__ __forceinline__ void red_add_v4_h2(__half* addr, unsigned h0,
                                              unsigned h1, unsigned h2_,
                                              unsigned h3) {
    asm volatile("red.global.add.noftz.v4.f16x2 [%0], {%1,%2,%3,%4};"
                 :: "l"(addr), "r"(h0), "r"(h1), "r"(h2_), "r"(h3)
                 : "memory");
}

// Per-axis decomposition of corner pair {c0, c0+1} into up to 2 bricks.
// w0/w1 = weight destined for in-brick position 0 / 1 on that axis.
struct Axis {
    int n;
    int b[2];
    float w0[2], w1[2];
};

__device__ __forceinline__ Axis axis_decomp(int c0, float wlo, float whi) {
    Axis a;
    a.n = 0;
    int bA = c0 >> 1;  // arithmetic shift: c0=-1 -> -1 (rejected below)
    if (!(c0 & 1)) {
        if ((unsigned)bA < BRICKS) {
            a.b[0] = bA; a.w0[0] = wlo; a.w1[0] = whi; a.n = 1;
        }
    } else {
        if ((unsigned)bA < BRICKS) {
            a.b[a.n] = bA; a.w0[a.n] = 0.0f; a.w1[a.n] = wlo; a.n++;
        }
        int bB = bA + 1;
        if ((unsigned)bB < BRICKS) {
            a.b[a.n] = bB; a.w0[a.n] = whi; a.w1[a.n] = 0.0f; a.n++;
        }
    }
    return a;
}

__device__ __forceinline__ void splat(float px, float py, float pz, float s) {
    // Match reference arithmetic exactly: p = ((g+1)*size - 1) * 0.5
    float x = ((px + 1.0f) * 256.0f - 1.0f) * 0.5f;
    float y = ((py + 1.0f) * 256.0f - 1.0f) * 0.5f;
    float z = ((pz + 1.0f) * 256.0f - 1.0f) * 0.5f;
    float x0f = floorf(x), y0f = floorf(y), z0f = floorf(z);
    int x0 = (int)x0f, y0 = (int)y0f, z0 = (int)z0f;
    float fx = x - x0f, fy = y - y0f, fz = z - z0f;

    Axis ax = axis_decomp(x0, 1.0f - fx, fx);
    Axis ay = axis_decomp(y0, 1.0f - fy, fy);
    Axis az = axis_decomp(z0, (1.0f - fz) * s, fz * s);  // fold sign into z

#pragma unroll
    for (int i = 0; i < 2; i++) {
        if (i >= az.n) break;
        float t0 = az.w0[i], t1 = az.w1[i];
        int zb = az.b[i] * BRICKS;
#pragma unroll
        for (int j = 0; j < 2; j++) {
            if (j >= ay.n) break;
            float a00 = t0 * ay.w0[j];  // z0,y0
            float a01 = t0 * ay.w1[j];  // z0,y1
            float a10 = t1 * ay.w0[j];  // z1,y0
            float a11 = t1 * ay.w1[j];  // z1,y1
            int rowb = (zb + ay.b[j]) * BRICKS;
#pragma unroll
            for (int k = 0; k < 2; k++) {
                if (k >= ax.n) break;
                float u0 = ax.w0[k], u1 = ax.w1[k];
                __half* p = g_hvol + (size_t)(rowb + ax.b[k]) * 8;
                // h2 lanes are x0,x1 within cell pairs (z,y) fixed:
                __half2 q0 = __floats2half2_rn(a00 * u0, a00 * u1); // z0y0
                __half2 q1 = __floats2half2_rn(a01 * u0, a01 * u1); // z0y1
                __half2 q2 = __floats2half2_rn(a10 * u0, a10 * u1); // z1y0
                __half2 q3 = __floats2half2_rn(a11 * u0, a11 * u1); // z1y1
                red_add_v4_h2(p,
                              *(unsigned*)&q0, *(unsigned*)&q1,
                              *(unsigned*)&q2, *(unsigned*)&q3);
            }
        }
    }
}

__global__ void scatter_kernel(const float* __restrict__ pred,
                               const float* __restrict__ gt,
                               const float* __restrict__ coords,
                               float* __restrict__ out, int n) {
    int i = blockIdx.x * blockDim.x + threadIdx.x;
    if (i == 0) out[0] = 0.0f;  // reduce kernel runs after us in stream order
    if (i >= n) return;

    // Streaming (evict-first) loads: keep L2 capacity for the volume.
    float cx = __ldcs(&coords[3 * i + 0]);
    float cy = __ldcs(&coords[3 * i + 1]);
    float cz = __ldcs(&coords[3 * i + 2]);
    float p0 = __ldcs(&pred[3 * i + 0]);
    float p1 = __ldcs(&pred[3 * i + 1]);
    float p2 = __ldcs(&pred[3 * i + 2]);
    float g0 = __ldcs(&gt[3 * i + 0]);
    float g1 = __ldcs(&gt[3 * i + 1]);
    float g2 = __ldcs(&gt[3 * i + 2]);

    splat(cx + p0, cy + p1, cz + p2,  1.0f);
    splat(cx + g0, cy + g1, cz + g2, -1.0f);
}

__device__ __forceinline__ float huber(float d) {
    float ad = fabsf(d);
    return (ad <= 1.0f) ? 0.5f * d * d : (ad - 0.5f);
}

__device__ __forceinline__ float huber_h2(unsigned h2bits) {
    __half2 h = *(__half2*)&h2bits;
    float2 f = __half22float2(h);
    return huber(f.x) + huber(f.y);
}

// 512 blocks x 256 threads; each thread handles exactly 16 uint4 (8 halves
// each) at stride RED_TOTAL -> 16 independent loads genuinely in flight.
// __launch_bounds__(256, 2) raises the register cap to 128/thread so ptxas
// can keep all 16 uint4 (64 regs) live; at 32 regs it silently serializes
// the loads into ~4-deep waves (observed R9/R10: regs=32, MLP_eff~5).
// NVOX/8 = 2097152 = 16 * 131072 exactly -> no bounds checks.
#define RED_BLOCKS 512
#define RED_THREADS 256
#define RED_TOTAL (RED_BLOCKS * RED_THREADS)
#define RED_ITERS 16

__global__ void __launch_bounds__(RED_THREADS, 2)
huber_reduce_kernel(float* __restrict__ out) {
    uint4* v = reinterpret_cast<uint4*>(g_hvol);
    const int tid = blockIdx.x * RED_THREADS + threadIdx.x;
    const uint4 zero = make_uint4(0u, 0u, 0u, 0u);

    uint4 a[RED_ITERS];
#pragma unroll
    for (int k = 0; k < RED_ITERS; k++)
        a[k] = v[tid + k * RED_TOTAL];

    // Re-zero for the next graph replay.
#pragma unroll
    for (int k = 0; k < RED_ITERS; k++)
        v[tid + k * RED_TOTAL] = zero;

    float acc = 0.0f;
#pragma unroll
    for (int k = 0; k < RED_ITERS; k++) {
        acc += huber_h2(a[k].x) + huber_h2(a[k].y)
             + huber_h2(a[k].z) + huber_h2(a[k].w);
    }

    // warp reduce
#pragma unroll
    for (int o = 16; o; o >>= 1) acc += __shfl_xor_sync(0xFFFFFFFFu, acc, o);

    __shared__ float sm[RED_THREADS / 32];
    int lane = threadIdx.x & 31;
    int wid = threadIdx.x >> 5;
    if (lane == 0) sm[wid] = acc;
    __syncthreads();
    if (wid == 0) {
        float vv = (lane < (RED_THREADS / 32)) ? sm[lane] : 0.0f;
#pragma unroll
        for (int o = 16; o; o >>= 1) vv += __shfl_xor_sync(0xFFFFFFFFu, vv, o);
        if (lane == 0) atomicAdd(out, vv);
    }
}

extern "C" void kernel_launch(void* const* d_in, const int* in_sizes, int n_in,
                              void* d_out, int out_size) {
    const float* pred   = (const float*)d_in[0];
    const float* gt     = (const float*)d_in[1];
    const float* coords = (const float*)d_in[2];
    float* out = (float*)d_out;

    int n = in_sizes[0] / 3;  // N_POINTS

    int threads = 256;
    int blocks = (n + threads - 1) / threads;
    scatter_kernel<<<blocks, threads>>>(pred, gt, coords, out, n);

    huber_reduce_kernel<<<RED_BLOCKS, RED_THREADS>>>(out);
}